// round 1
// baseline (speedup 1.0000x reference)
#include <cuda_runtime.h>
#include <cuda_bf16.h>
#include <cstdint>

// Problem constants
#define B_  4
#define S_  2048
#define H_  1024
#define NH_ 16
#define HD_ 64
#define M_  (B_ * S_)          // 8192 rows

// ---------------------------------------------------------------------------
// Scratch (allocation-free): Q/K/V in [b, nh, s, hd], ctx in [b, s, h]
// ---------------------------------------------------------------------------
__device__ float g_q[(size_t)B_ * NH_ * S_ * HD_];
__device__ float g_k[(size_t)B_ * NH_ * S_ * HD_];
__device__ float g_v[(size_t)B_ * NH_ * S_ * HD_];
__device__ float g_ctx[(size_t)M_ * H_];

// ---------------------------------------------------------------------------
// Kernel 1: fused QKV projection.  C = X @ W + b for W in {Wq,Wk,Wv}
// X: [8192,1024] row-major, W: [1024,1024] row-major, out scattered to
// [b, nh, s, hd].
// 128x128x16 tile, 256 threads, 8x8 micro-tile.
// ---------------------------------------------------------------------------
#define TM 128
#define TN 128
#define TK 16

__global__ __launch_bounds__(256) void qkv_gemm_kernel(
    const float* __restrict__ X,
    const float* __restrict__ Wq, const float* __restrict__ bq,
    const float* __restrict__ Wk, const float* __restrict__ bk,
    const float* __restrict__ Wv, const float* __restrict__ bv)
{
    const float* W; const float* bias; float* out;
    if (blockIdx.z == 0)      { W = Wq; bias = bq; out = g_q; }
    else if (blockIdx.z == 1) { W = Wk; bias = bk; out = g_k; }
    else                      { W = Wv; bias = bv; out = g_v; }

    __shared__ float As[TK][TM + 4];
    __shared__ float Bs[TK][TN + 4];

    const int t  = threadIdx.x;
    const int tx = t & 15;          // 0..15
    const int ty = t >> 4;          // 0..15
    const int m0 = blockIdx.y * TM;
    const int n0 = blockIdx.x * TN;

    float acc[8][8] = {};

    for (int k0 = 0; k0 < H_; k0 += TK) {
        // A tile: 128 rows x 16 k  (512 float4, 2 per thread), store transposed
        #pragma unroll
        for (int i = 0; i < 2; i++) {
            int idx = t + i * 256;               // 0..511
            int row = idx >> 2;                  // 0..127
            int kq  = (idx & 3) * 4;             // 0,4,8,12
            float4 a4 = *(const float4*)&X[(size_t)(m0 + row) * H_ + k0 + kq];
            As[kq + 0][row] = a4.x; As[kq + 1][row] = a4.y;
            As[kq + 2][row] = a4.z; As[kq + 3][row] = a4.w;
        }
        // B tile: 16 k x 128 n  (512 float4, 2 per thread)
        #pragma unroll
        for (int i = 0; i < 2; i++) {
            int idx = t + i * 256;
            int row = idx >> 5;                  // 0..15
            int c4  = (idx & 31) * 4;            // 0..124
            *(float4*)&Bs[row][c4] =
                *(const float4*)&W[(size_t)(k0 + row) * H_ + n0 + c4];
        }
        __syncthreads();

        #pragma unroll
        for (int kk = 0; kk < TK; kk++) {
            float af[8], bf[8];
            #pragma unroll
            for (int i = 0; i < 8; i++) af[i] = As[kk][ty * 8 + i];
            #pragma unroll
            for (int j = 0; j < 8; j++) bf[j] = Bs[kk][tx * 8 + j];
            #pragma unroll
            for (int i = 0; i < 8; i++)
                #pragma unroll
                for (int j = 0; j < 8; j++)
                    acc[i][j] += af[i] * bf[j];
        }
        __syncthreads();
    }

    // epilogue: bias + scatter to [b, nh, s, hd]
    #pragma unroll
    for (int i = 0; i < 8; i++) {
        int m = m0 + ty * 8 + i;
        int b = m >> 11;                 // / 2048
        int s = m & (S_ - 1);
        #pragma unroll
        for (int j = 0; j < 8; j++) {
            int n  = n0 + tx * 8 + j;
            int nh = n >> 6;
            int d  = n & 63;
            out[(((size_t)(b * NH_ + nh)) * S_ + s) * HD_ + d] = acc[i][j] + bias[n];
        }
    }
}

// ---------------------------------------------------------------------------
// Kernel 2: flash attention, one (64-row q-tile, head) per block.
// Br = Bc = 64, HD = 64. 256 threads, 4x4 micro-tile for both GEMMs.
// Dynamic smem: Qs[64][68], KVs[64][68], Ss[64][68], stats.
// ---------------------------------------------------------------------------
#define ABR 64
#define ABC 64
#define APAD 68

#define ATT_SMEM_FLOATS (3 * ABR * APAD + 3 * ABR)
#define ATT_SMEM_BYTES  (ATT_SMEM_FLOATS * 4)

__global__ __launch_bounds__(256) void attn_kernel()
{
    extern __shared__ float smem[];
    float* Qs  = smem;                     // [64][68]
    float* KVs = Qs  + ABR * APAD;         // [64][68]
    float* Ss  = KVs + ABR * APAD;         // [64][68]
    float* row_m     = Ss + ABR * APAD;    // [64]
    float* row_l     = row_m + ABR;        // [64]
    float* row_scale = row_l + ABR;        // [64]

    const int bh = blockIdx.y;             // 0..63
    const int b  = bh >> 4;
    const int h  = bh & 15;
    const int q0 = blockIdx.x * ABR;

    const float* Qp = g_q + (size_t)bh * S_ * HD_;
    const float* Kp = g_k + (size_t)bh * S_ * HD_;
    const float* Vp = g_v + (size_t)bh * S_ * HD_;

    const int t    = threadIdx.x;
    const int tx   = t & 15;
    const int ty   = t >> 4;
    const int warp = t >> 5;
    const int lane = t & 31;

    // Load Q tile: 64x64 floats = 1024 float4, 4 per thread
    #pragma unroll
    for (int i = 0; i < 4; i++) {
        int idx = t + i * 256;
        int r   = idx >> 4;
        int c4  = (idx & 15) * 4;
        *(float4*)&Qs[r * APAD + c4] =
            *(const float4*)&Qp[(size_t)(q0 + r) * HD_ + c4];
    }
    if (t < ABR) { row_m[t] = -1e30f; row_l[t] = 0.0f; }

    float o[4][4] = {};
    const float sm_scale = 0.125f;         // 1/sqrt(64)

    for (int kt = 0; kt < S_; kt += ABC) {
        __syncthreads();  // prior PV done (and Q/stats ready on iter 0)

        // Load K tile
        #pragma unroll
        for (int i = 0; i < 4; i++) {
            int idx = t + i * 256;
            int r   = idx >> 4;
            int c4  = (idx & 15) * 4;
            *(float4*)&KVs[r * APAD + c4] =
                *(const float4*)&Kp[(size_t)(kt + r) * HD_ + c4];
        }
        __syncthreads();

        // S = Q @ K^T * scale  (4x4 per thread)
        float s[4][4] = {};
        #pragma unroll
        for (int d = 0; d < HD_; d++) {
            float qf[4], kf[4];
            #pragma unroll
            for (int i = 0; i < 4; i++) qf[i] = Qs[(ty * 4 + i) * APAD + d];
            #pragma unroll
            for (int j = 0; j < 4; j++) kf[j] = KVs[(tx * 4 + j) * APAD + d];
            #pragma unroll
            for (int i = 0; i < 4; i++)
                #pragma unroll
                for (int j = 0; j < 4; j++)
                    s[i][j] += qf[i] * kf[j];
        }
        #pragma unroll
        for (int i = 0; i < 4; i++)
            #pragma unroll
            for (int j = 0; j < 4; j++)
                Ss[(ty * 4 + i) * APAD + tx * 4 + j] = s[i][j] * sm_scale;
        __syncthreads();

        // Load V tile into KVs (K reads are complete) — overlaps with softmax
        #pragma unroll
        for (int i = 0; i < 4; i++) {
            int idx = t + i * 256;
            int r   = idx >> 4;
            int c4  = (idx & 15) * 4;
            *(float4*)&KVs[r * APAD + c4] =
                *(const float4*)&Vp[(size_t)(kt + r) * HD_ + c4];
        }

        // Online softmax: warp w owns rows w*8 .. w*8+7 (2 elems per lane)
        #pragma unroll
        for (int rr = 0; rr < 8; rr++) {
            int r = warp * 8 + rr;
            float v0 = Ss[r * APAD + lane];
            float v1 = Ss[r * APAD + lane + 32];
            float mx = fmaxf(v0, v1);
            #pragma unroll
            for (int off = 16; off; off >>= 1)
                mx = fmaxf(mx, __shfl_xor_sync(0xFFFFFFFFu, mx, off));
            float m_old = row_m[r];
            float m_new = fmaxf(m_old, mx);
            float p0 = __expf(v0 - m_new);
            float p1 = __expf(v1 - m_new);
            Ss[r * APAD + lane]      = p0;
            Ss[r * APAD + lane + 32] = p1;
            float sum = p0 + p1;
            #pragma unroll
            for (int off = 16; off; off >>= 1)
                sum += __shfl_xor_sync(0xFFFFFFFFu, sum, off);
            if (lane == 0) {
                float sc = __expf(m_old - m_new);
                row_l[r]     = row_l[r] * sc + sum;
                row_m[r]     = m_new;
                row_scale[r] = sc;
            }
        }
        __syncthreads();

        // Rescale accumulators
        #pragma unroll
        for (int i = 0; i < 4; i++) {
            float sc = row_scale[ty * 4 + i];
            #pragma unroll
            for (int j = 0; j < 4; j++) o[i][j] *= sc;
        }

        // O += P @ V  (4x4 per thread)
        #pragma unroll
        for (int c = 0; c < ABC; c++) {
            float pf[4], vf[4];
            #pragma unroll
            for (int i = 0; i < 4; i++) pf[i] = Ss[(ty * 4 + i) * APAD + c];
            #pragma unroll
            for (int j = 0; j < 4; j++) vf[j] = KVs[c * APAD + tx * 4 + j];
            #pragma unroll
            for (int i = 0; i < 4; i++)
                #pragma unroll
                for (int j = 0; j < 4; j++)
                    o[i][j] += pf[i] * vf[j];
        }
    }

    // Epilogue: normalize, write ctx in [b, s, h]
    #pragma unroll
    for (int i = 0; i < 4; i++) {
        int r = ty * 4 + i;
        float inv = 1.0f / row_l[r];
        int srow = q0 + r;
        #pragma unroll
        for (int j = 0; j < 4; j++) {
            int c = tx * 4 + j;
            g_ctx[((size_t)(b * S_ + srow)) * H_ + h * HD_ + c] = o[i][j] * inv;
        }
    }
}

// ---------------------------------------------------------------------------
// Kernel 3: output projection.  out = ctx @ Wo + bo  (plain row-major store)
// ---------------------------------------------------------------------------
__global__ __launch_bounds__(256) void oproj_gemm_kernel(
    const float* __restrict__ Wo, const float* __restrict__ bo,
    float* __restrict__ out)
{
    __shared__ float As[TK][TM + 4];
    __shared__ float Bs[TK][TN + 4];

    const int t  = threadIdx.x;
    const int tx = t & 15;
    const int ty = t >> 4;
    const int m0 = blockIdx.y * TM;
    const int n0 = blockIdx.x * TN;

    float acc[8][8] = {};

    for (int k0 = 0; k0 < H_; k0 += TK) {
        #pragma unroll
        for (int i = 0; i < 2; i++) {
            int idx = t + i * 256;
            int row = idx >> 2;
            int kq  = (idx & 3) * 4;
            float4 a4 = *(const float4*)&g_ctx[(size_t)(m0 + row) * H_ + k0 + kq];
            As[kq + 0][row] = a4.x; As[kq + 1][row] = a4.y;
            As[kq + 2][row] = a4.z; As[kq + 3][row] = a4.w;
        }
        #pragma unroll
        for (int i = 0; i < 2; i++) {
            int idx = t + i * 256;
            int row = idx >> 5;
            int c4  = (idx & 31) * 4;
            *(float4*)&Bs[row][c4] =
                *(const float4*)&Wo[(size_t)(k0 + row) * H_ + n0 + c4];
        }
        __syncthreads();

        #pragma unroll
        for (int kk = 0; kk < TK; kk++) {
            float af[8], bf[8];
            #pragma unroll
            for (int i = 0; i < 8; i++) af[i] = As[kk][ty * 8 + i];
            #pragma unroll
            for (int j = 0; j < 8; j++) bf[j] = Bs[kk][tx * 8 + j];
            #pragma unroll
            for (int i = 0; i < 8; i++)
                #pragma unroll
                for (int j = 0; j < 8; j++)
                    acc[i][j] += af[i] * bf[j];
        }
        __syncthreads();
    }

    #pragma unroll
    for (int i = 0; i < 8; i++) {
        int m = m0 + ty * 8 + i;
        #pragma unroll
        for (int j = 0; j < 8; j++) {
            int n = n0 + tx * 8 + j;
            out[(size_t)m * H_ + n] = acc[i][j] + bo[n];
        }
    }
}

// ---------------------------------------------------------------------------
// Launch
// ---------------------------------------------------------------------------
extern "C" void kernel_launch(void* const* d_in, const int* in_sizes, int n_in,
                              void* d_out, int out_size)
{
    const float* X  = (const float*)d_in[0];
    const float* Wq = (const float*)d_in[1];
    const float* bq = (const float*)d_in[2];
    const float* Wk = (const float*)d_in[3];
    const float* bk = (const float*)d_in[4];
    const float* Wv = (const float*)d_in[5];
    const float* bv = (const float*)d_in[6];
    const float* Wo = (const float*)d_in[7];
    const float* bo = (const float*)d_in[8];
    float* out = (float*)d_out;

    // Attention kernel needs > 48KB smem
    static bool attr_set = false;
    if (!attr_set) {
        cudaFuncSetAttribute(attn_kernel,
                             cudaFuncAttributeMaxDynamicSharedMemorySize,
                             ATT_SMEM_BYTES);
        attr_set = true;
    }

    dim3 gproj(H_ / TN, M_ / TM, 3);        // (8, 64, 3)
    qkv_gemm_kernel<<<gproj, 256>>>(X, Wq, bq, Wk, bk, Wv, bv);

    dim3 gattn(S_ / ABR, B_ * NH_);         // (32, 64)
    attn_kernel<<<gattn, 256, ATT_SMEM_BYTES>>>();

    dim3 gout(H_ / TN, M_ / TM);            // (8, 64)
    oproj_gemm_kernel<<<gout, 256>>>(Wo, bo, out);
}

// round 3
// speedup vs baseline: 4.4073x; 4.4073x over previous
#include <cuda_runtime.h>
#include <cuda_bf16.h>
#include <cstdint>

// Problem constants
#define B_  4
#define S_  2048
#define H_  1024
#define NH_ 16
#define HD_ 64
#define M_  (B_ * S_)          // 8192 rows

// ---------------------------------------------------------------------------
// Scratch: split-bf16 (hi/lo) Q/K/V in [bh, s, hd], ctx in [m, h]
// ---------------------------------------------------------------------------
__device__ __nv_bfloat16 g_q_hi[(size_t)B_ * NH_ * S_ * HD_];
__device__ __nv_bfloat16 g_q_lo[(size_t)B_ * NH_ * S_ * HD_];
__device__ __nv_bfloat16 g_k_hi[(size_t)B_ * NH_ * S_ * HD_];
__device__ __nv_bfloat16 g_k_lo[(size_t)B_ * NH_ * S_ * HD_];
__device__ __nv_bfloat16 g_v_hi[(size_t)B_ * NH_ * S_ * HD_];
__device__ __nv_bfloat16 g_v_lo[(size_t)B_ * NH_ * S_ * HD_];
__device__ __nv_bfloat16 g_ctx_hi[(size_t)M_ * H_];
__device__ __nv_bfloat16 g_ctx_lo[(size_t)M_ * H_];

// ---------------------------------------------------------------------------
// Helpers: split fp32 -> (hi, lo) bf16, packed as bf16x2 in u32
// ---------------------------------------------------------------------------
__device__ __forceinline__ void split_pack(float x0, float x1,
                                           uint32_t& hi, uint32_t& lo)
{
    __nv_bfloat16 h0 = __float2bfloat16_rn(x0);
    __nv_bfloat16 h1 = __float2bfloat16_rn(x1);
    float r0 = x0 - __bfloat162float(h0);
    float r1 = x1 - __bfloat162float(h1);
    __nv_bfloat16 l0 = __float2bfloat16_rn(r0);
    __nv_bfloat16 l1 = __float2bfloat16_rn(r1);
    hi = (uint32_t)__bfloat16_as_ushort(h0) |
         ((uint32_t)__bfloat16_as_ushort(h1) << 16);
    lo = (uint32_t)__bfloat16_as_ushort(l0) |
         ((uint32_t)__bfloat16_as_ushort(l1) << 16);
}

__device__ __forceinline__ uint32_t smem_u32(const void* p)
{
    return (uint32_t)__cvta_generic_to_shared(p);
}

__device__ __forceinline__ void ldsm4(uint32_t& r0, uint32_t& r1,
                                      uint32_t& r2, uint32_t& r3, uint32_t a)
{
    asm volatile("ldmatrix.sync.aligned.m8n8.x4.shared.b16 {%0,%1,%2,%3},[%4];"
                 : "=r"(r0), "=r"(r1), "=r"(r2), "=r"(r3) : "r"(a));
}

__device__ __forceinline__ void ldsm4t(uint32_t& r0, uint32_t& r1,
                                       uint32_t& r2, uint32_t& r3, uint32_t a)
{
    asm volatile("ldmatrix.sync.aligned.m8n8.x4.trans.shared.b16 {%0,%1,%2,%3},[%4];"
                 : "=r"(r0), "=r"(r1), "=r"(r2), "=r"(r3) : "r"(a));
}

__device__ __forceinline__ void mma_bf16(float* c, const uint32_t a[4],
                                         uint32_t b0, uint32_t b1)
{
    asm volatile(
        "mma.sync.aligned.m16n8k16.row.col.f32.bf16.bf16.f32 "
        "{%0,%1,%2,%3}, {%4,%5,%6,%7}, {%8,%9}, {%0,%1,%2,%3};\n"
        : "+f"(c[0]), "+f"(c[1]), "+f"(c[2]), "+f"(c[3])
        : "r"(a[0]), "r"(a[1]), "r"(a[2]), "r"(a[3]), "r"(b0), "r"(b1));
}

// ---------------------------------------------------------------------------
// Kernel 1: QKV projection (tensor core, split bf16 3-pass).
// C = X @ W + b ; z selects {Q (scaled by 0.125), K, V}; outputs hi/lo bf16
// in [bh, s, hd] layout.  CTA tile 128x128, K-step 32, 256 threads (8 warps,
// warp tile 64x32).
// ---------------------------------------------------------------------------
#define PLDA 40    // A smem row stride (elems), tile [128 m][32 k]
#define PLDB 136   // B smem row stride (elems), tile [32 k][128 n]

__global__ __launch_bounds__(256) void qkv_gemm_tc(
    const float* __restrict__ X,
    const float* __restrict__ Wq, const float* __restrict__ bq,
    const float* __restrict__ Wk, const float* __restrict__ bk,
    const float* __restrict__ Wv, const float* __restrict__ bv)
{
    const float* W; const float* bias;
    __nv_bfloat16 *oh, *ol; float scale;
    if (blockIdx.z == 0)      { W = Wq; bias = bq; oh = g_q_hi; ol = g_q_lo; scale = 0.125f; }
    else if (blockIdx.z == 1) { W = Wk; bias = bk; oh = g_k_hi; ol = g_k_lo; scale = 1.0f; }
    else                      { W = Wv; bias = bv; oh = g_v_hi; ol = g_v_lo; scale = 1.0f; }

    __shared__ __nv_bfloat16 Ah[128 * PLDA];
    __shared__ __nv_bfloat16 Al[128 * PLDA];
    __shared__ __nv_bfloat16 Bh[32 * PLDB];
    __shared__ __nv_bfloat16 Bl[32 * PLDB];

    const int t = threadIdx.x, lane = t & 31, warp = t >> 5;
    const int wm = warp & 1, wn = warp >> 1;
    const int m0 = blockIdx.y * 128, n0 = blockIdx.x * 128;

    float acc[4][4][4] = {};

    for (int k0 = 0; k0 < H_; k0 += 32) {
        // stage A (X) with inline split
        #pragma unroll
        for (int j = 0; j < 4; j++) {
            int i = t + j * 256;
            int row = i >> 3, c4 = (i & 7) * 4;
            float4 v = *(const float4*)&X[(size_t)(m0 + row) * H_ + k0 + c4];
            uint32_t h0, l0, h1, l1;
            split_pack(v.x, v.y, h0, l0);
            split_pack(v.z, v.w, h1, l1);
            *(uint2*)&Ah[row * PLDA + c4] = make_uint2(h0, h1);
            *(uint2*)&Al[row * PLDA + c4] = make_uint2(l0, l1);
        }
        // stage B (W) with inline split
        #pragma unroll
        for (int j = 0; j < 4; j++) {
            int i = t + j * 256;
            int row = i >> 5, c4 = (i & 31) * 4;
            float4 v = *(const float4*)&W[(size_t)(k0 + row) * H_ + n0 + c4];
            uint32_t h0, l0, h1, l1;
            split_pack(v.x, v.y, h0, l0);
            split_pack(v.z, v.w, h1, l1);
            *(uint2*)&Bh[row * PLDB + c4] = make_uint2(h0, h1);
            *(uint2*)&Bl[row * PLDB + c4] = make_uint2(l0, l1);
        }
        __syncthreads();

        #pragma unroll
        for (int kk = 0; kk < 2; kk++) {
            uint32_t ah[4][4], al[4][4];
            const int arow = wm * 64 + (lane & 7) + ((lane >> 3) & 1) * 8;
            const int acol = kk * 16 + (lane >> 4) * 8;
            #pragma unroll
            for (int mf = 0; mf < 4; mf++) {
                uint32_t ad = smem_u32(&Ah[(arow + mf * 16) * PLDA + acol]);
                ldsm4(ah[mf][0], ah[mf][1], ah[mf][2], ah[mf][3], ad);
                uint32_t ad2 = smem_u32(&Al[(arow + mf * 16) * PLDA + acol]);
                ldsm4(al[mf][0], al[mf][1], al[mf][2], al[mf][3], ad2);
            }
            uint32_t bh[4][2], bl[4][2];
            const int brow = kk * 16 + (lane & 7) + ((lane >> 3) & 1) * 8;
            #pragma unroll
            for (int nb = 0; nb < 2; nb++) {
                const int bcol = wn * 32 + nb * 16 + (lane >> 4) * 8;
                uint32_t bd = smem_u32(&Bh[brow * PLDB + bcol]);
                ldsm4t(bh[2*nb][0], bh[2*nb][1], bh[2*nb+1][0], bh[2*nb+1][1], bd);
                uint32_t bd2 = smem_u32(&Bl[brow * PLDB + bcol]);
                ldsm4t(bl[2*nb][0], bl[2*nb][1], bl[2*nb+1][0], bl[2*nb+1][1], bd2);
            }
            #pragma unroll
            for (int mf = 0; mf < 4; mf++)
                #pragma unroll
                for (int nf = 0; nf < 4; nf++) {
                    mma_bf16(acc[mf][nf], ah[mf], bh[nf][0], bh[nf][1]);
                    mma_bf16(acc[mf][nf], ah[mf], bl[nf][0], bl[nf][1]);
                    mma_bf16(acc[mf][nf], al[mf], bh[nf][0], bh[nf][1]);
                }
        }
        __syncthreads();
    }

    // epilogue: bias, scale, split, scatter to [bh, s, hd]
    const int g = lane >> 2, tq = lane & 3;
    #pragma unroll
    for (int mf = 0; mf < 4; mf++) {
        int r0 = m0 + wm * 64 + mf * 16 + g;
        int r1 = r0 + 8;
        int b0r = r0 >> 11, s0 = r0 & (S_ - 1);
        int b1r = r1 >> 11, s1 = r1 & (S_ - 1);
        #pragma unroll
        for (int nf = 0; nf < 4; nf++) {
            int n = n0 + wn * 32 + nf * 8 + tq * 2;
            float bia0 = bias[n], bia1 = bias[n + 1];
            int h = n >> 6, d = n & 63;
            size_t i0 = (((size_t)(b0r * NH_ + h)) * S_ + s0) * HD_ + d;
            size_t i1 = (((size_t)(b1r * NH_ + h)) * S_ + s1) * HD_ + d;
            uint32_t hi, lo;
            split_pack((acc[mf][nf][0] + bia0) * scale,
                       (acc[mf][nf][1] + bia1) * scale, hi, lo);
            *(uint32_t*)&oh[i0] = hi; *(uint32_t*)&ol[i0] = lo;
            split_pack((acc[mf][nf][2] + bia0) * scale,
                       (acc[mf][nf][3] + bia1) * scale, hi, lo);
            *(uint32_t*)&oh[i1] = hi; *(uint32_t*)&ol[i1] = lo;
        }
    }
}

// ---------------------------------------------------------------------------
// Kernel 2: flash attention on tensor cores (split bf16 3-pass).
// Block: 256 threads (8 warps), q-tile 128 rows, kv-tile 64, HD=64.
// Warp w owns q rows [w*16, w*16+16).  S and P live entirely in fragments.
// ---------------------------------------------------------------------------
#define ALDQ 72
#define ALDK 72
#define ATT_SMEM_ELEMS (2 * 128 * ALDQ + 4 * 64 * ALDK)
#define ATT_SMEM_BYTES (ATT_SMEM_ELEMS * 2)

__global__ __launch_bounds__(256) void attn_tc()
{
    extern __shared__ __nv_bfloat16 sm[];
    __nv_bfloat16* Qh = sm;
    __nv_bfloat16* Ql = Qh + 128 * ALDQ;
    __nv_bfloat16* Kh = Ql + 128 * ALDQ;
    __nv_bfloat16* Kl = Kh + 64 * ALDK;
    __nv_bfloat16* Vh = Kl + 64 * ALDK;
    __nv_bfloat16* Vl = Vh + 64 * ALDK;

    const int bh = blockIdx.y;
    const int q0 = blockIdx.x * 128;
    const size_t qbase = ((size_t)bh * S_ + q0) * HD_;

    const int t = threadIdx.x, lane = t & 31, warp = t >> 5;
    const int g = lane >> 2, tq = lane & 3;

    // load Q tile (hi + lo), 128x64 bf16 each
    #pragma unroll
    for (int j = 0; j < 4; j++) {
        int i = t + j * 256;
        int row = i >> 3, c8 = (i & 7) * 8;
        *(uint4*)&Qh[row * ALDQ + c8] = *(const uint4*)&g_q_hi[qbase + row * HD_ + c8];
        *(uint4*)&Ql[row * ALDQ + c8] = *(const uint4*)&g_q_lo[qbase + row * HD_ + c8];
    }

    float o[8][4] = {};
    float mrow0 = -1e30f, mrow1 = -1e30f;
    float lrow0 = 0.0f, lrow1 = 0.0f;

    for (int kt = 0; kt < S_; kt += 64) {
        const size_t kvb = ((size_t)bh * S_ + kt) * HD_;
        // stage K and V tiles (hi + lo)
        #pragma unroll
        for (int j = 0; j < 2; j++) {
            int i = t + j * 256;
            int row = i >> 3, c8 = (i & 7) * 8;
            *(uint4*)&Kh[row * ALDK + c8] = *(const uint4*)&g_k_hi[kvb + row * HD_ + c8];
            *(uint4*)&Kl[row * ALDK + c8] = *(const uint4*)&g_k_lo[kvb + row * HD_ + c8];
            *(uint4*)&Vh[row * ALDK + c8] = *(const uint4*)&g_v_hi[kvb + row * HD_ + c8];
            *(uint4*)&Vl[row * ALDK + c8] = *(const uint4*)&g_v_lo[kvb + row * HD_ + c8];
        }
        __syncthreads();

        // ---- S = Qscaled @ K^T (fp32 fragments) ----
        float sacc[8][4] = {};
        #pragma unroll
        for (int kk = 0; kk < 4; kk++) {
            uint32_t qa_h[4], qa_l[4];
            const int arow = warp * 16 + (lane & 7) + ((lane >> 3) & 1) * 8;
            const int acol = kk * 16 + (lane >> 4) * 8;
            ldsm4(qa_h[0], qa_h[1], qa_h[2], qa_h[3], smem_u32(&Qh[arow * ALDQ + acol]));
            ldsm4(qa_l[0], qa_l[1], qa_l[2], qa_l[3], smem_u32(&Ql[arow * ALDQ + acol]));

            const int brow_k = (lane & 7) + ((lane >> 4) & 1) * 8;   // n (kv) part
            const int bcol_k = kk * 16 + ((lane >> 3) & 1) * 8;      // k (hd) part
            #pragma unroll
            for (int nb = 0; nb < 4; nb++) {
                uint32_t kb_h[4], kb_l[4];
                ldsm4(kb_h[0], kb_h[1], kb_h[2], kb_h[3],
                      smem_u32(&Kh[(nb * 16 + brow_k) * ALDK + bcol_k]));
                ldsm4(kb_l[0], kb_l[1], kb_l[2], kb_l[3],
                      smem_u32(&Kl[(nb * 16 + brow_k) * ALDK + bcol_k]));
                mma_bf16(sacc[nb*2],   qa_h, kb_h[0], kb_h[1]);
                mma_bf16(sacc[nb*2],   qa_h, kb_l[0], kb_l[1]);
                mma_bf16(sacc[nb*2],   qa_l, kb_h[0], kb_h[1]);
                mma_bf16(sacc[nb*2+1], qa_h, kb_h[2], kb_h[3]);
                mma_bf16(sacc[nb*2+1], qa_h, kb_l[2], kb_l[3]);
                mma_bf16(sacc[nb*2+1], qa_l, kb_h[2], kb_h[3]);
            }
        }

        // ---- online softmax (rows g and g+8, per lane-quad) ----
        float mx0 = -1e30f, mx1 = -1e30f;
        #pragma unroll
        for (int nf = 0; nf < 8; nf++) {
            mx0 = fmaxf(mx0, fmaxf(sacc[nf][0], sacc[nf][1]));
            mx1 = fmaxf(mx1, fmaxf(sacc[nf][2], sacc[nf][3]));
        }
        mx0 = fmaxf(mx0, __shfl_xor_sync(0xFFFFFFFFu, mx0, 1));
        mx0 = fmaxf(mx0, __shfl_xor_sync(0xFFFFFFFFu, mx0, 2));
        mx1 = fmaxf(mx1, __shfl_xor_sync(0xFFFFFFFFu, mx1, 1));
        mx1 = fmaxf(mx1, __shfl_xor_sync(0xFFFFFFFFu, mx1, 2));
        float mn0 = fmaxf(mrow0, mx0), mn1 = fmaxf(mrow1, mx1);
        float es0 = __expf(mrow0 - mn0), es1 = __expf(mrow1 - mn1);
        mrow0 = mn0; mrow1 = mn1;

        float sum0 = 0.0f, sum1 = 0.0f;
        #pragma unroll
        for (int nf = 0; nf < 8; nf++) {
            sacc[nf][0] = __expf(sacc[nf][0] - mn0);
            sacc[nf][1] = __expf(sacc[nf][1] - mn0);
            sacc[nf][2] = __expf(sacc[nf][2] - mn1);
            sacc[nf][3] = __expf(sacc[nf][3] - mn1);
            sum0 += sacc[nf][0] + sacc[nf][1];
            sum1 += sacc[nf][2] + sacc[nf][3];
        }
        sum0 += __shfl_xor_sync(0xFFFFFFFFu, sum0, 1);
        sum0 += __shfl_xor_sync(0xFFFFFFFFu, sum0, 2);
        sum1 += __shfl_xor_sync(0xFFFFFFFFu, sum1, 1);
        sum1 += __shfl_xor_sync(0xFFFFFFFFu, sum1, 2);
        lrow0 = lrow0 * es0 + sum0;
        lrow1 = lrow1 * es1 + sum1;

        #pragma unroll
        for (int nf = 0; nf < 8; nf++) {
            o[nf][0] *= es0; o[nf][1] *= es0;
            o[nf][2] *= es1; o[nf][3] *= es1;
        }

        // ---- O += P @ V ----
        #pragma unroll
        for (int kb = 0; kb < 4; kb++) {
            // P fragment (A, m16k16) from two adjacent score n8-fragments
            uint32_t pa_h[4], pa_l[4];
            split_pack(sacc[2*kb][0],   sacc[2*kb][1],   pa_h[0], pa_l[0]);
            split_pack(sacc[2*kb][2],   sacc[2*kb][3],   pa_h[1], pa_l[1]);
            split_pack(sacc[2*kb+1][0], sacc[2*kb+1][1], pa_h[2], pa_l[2]);
            split_pack(sacc[2*kb+1][2], sacc[2*kb+1][3], pa_h[3], pa_l[3]);

            const int vrow = kb * 16 + (lane & 7) + ((lane >> 3) & 1) * 8;  // k (kv)
            #pragma unroll
            for (int nb2 = 0; nb2 < 4; nb2++) {
                const int vcol = nb2 * 16 + ((lane >> 4) & 1) * 8;          // n (hd)
                uint32_t vb_h[4], vb_l[4];
                ldsm4t(vb_h[0], vb_h[1], vb_h[2], vb_h[3],
                       smem_u32(&Vh[vrow * ALDK + vcol]));
                ldsm4t(vb_l[0], vb_l[1], vb_l[2], vb_l[3],
                       smem_u32(&Vl[vrow * ALDK + vcol]));
                mma_bf16(o[nb2*2],   pa_h, vb_h[0], vb_h[1]);
                mma_bf16(o[nb2*2],   pa_h, vb_l[0], vb_l[1]);
                mma_bf16(o[nb2*2],   pa_l, vb_h[0], vb_h[1]);
                mma_bf16(o[nb2*2+1], pa_h, vb_h[2], vb_h[3]);
                mma_bf16(o[nb2*2+1], pa_h, vb_l[2], vb_l[3]);
                mma_bf16(o[nb2*2+1], pa_l, vb_h[2], vb_h[3]);
            }
        }
        __syncthreads();
    }

    // epilogue: normalize, split, write ctx [m, h*64+d]
    const float inv0 = 1.0f / lrow0, inv1 = 1.0f / lrow1;
    const int b = bh >> 4, h = bh & 15;
    const int mr0 = b * S_ + q0 + warp * 16 + g;
    const int mr1 = mr0 + 8;
    #pragma unroll
    for (int nf = 0; nf < 8; nf++) {
        int col = h * HD_ + nf * 8 + tq * 2;
        uint32_t hi, lo;
        split_pack(o[nf][0] * inv0, o[nf][1] * inv0, hi, lo);
        *(uint32_t*)&g_ctx_hi[(size_t)mr0 * H_ + col] = hi;
        *(uint32_t*)&g_ctx_lo[(size_t)mr0 * H_ + col] = lo;
        split_pack(o[nf][2] * inv1, o[nf][3] * inv1, hi, lo);
        *(uint32_t*)&g_ctx_hi[(size_t)mr1 * H_ + col] = hi;
        *(uint32_t*)&g_ctx_lo[(size_t)mr1 * H_ + col] = lo;
    }
}

// ---------------------------------------------------------------------------
// Kernel 3: output projection.  out = ctx @ Wo + bo (fp32 out).
// ctx already split bf16; Wo split inline.  Same tiling as kernel 1.
// ---------------------------------------------------------------------------
__global__ __launch_bounds__(256) void oproj_tc(
    const float* __restrict__ Wo, const float* __restrict__ bo,
    float* __restrict__ out)
{
    __shared__ __nv_bfloat16 Ah[128 * PLDA];
    __shared__ __nv_bfloat16 Al[128 * PLDA];
    __shared__ __nv_bfloat16 Bh[32 * PLDB];
    __shared__ __nv_bfloat16 Bl[32 * PLDB];

    const int t = threadIdx.x, lane = t & 31, warp = t >> 5;
    const int wm = warp & 1, wn = warp >> 1;
    const int m0 = blockIdx.y * 128, n0 = blockIdx.x * 128;

    float acc[4][4][4] = {};

    for (int k0 = 0; k0 < H_; k0 += 32) {
        // stage A from pre-split ctx
        #pragma unroll
        for (int j = 0; j < 2; j++) {
            int i = t + j * 256;
            int row = i >> 2, c8 = (i & 3) * 8;
            *(uint4*)&Ah[row * PLDA + c8] =
                *(const uint4*)&g_ctx_hi[(size_t)(m0 + row) * H_ + k0 + c8];
            *(uint4*)&Al[row * PLDA + c8] =
                *(const uint4*)&g_ctx_lo[(size_t)(m0 + row) * H_ + k0 + c8];
        }
        // stage B (Wo) with inline split
        #pragma unroll
        for (int j = 0; j < 4; j++) {
            int i = t + j * 256;
            int row = i >> 5, c4 = (i & 31) * 4;
            float4 v = *(const float4*)&Wo[(size_t)(k0 + row) * H_ + n0 + c4];
            uint32_t h0, l0, h1, l1;
            split_pack(v.x, v.y, h0, l0);
            split_pack(v.z, v.w, h1, l1);
            *(uint2*)&Bh[row * PLDB + c4] = make_uint2(h0, h1);
            *(uint2*)&Bl[row * PLDB + c4] = make_uint2(l0, l1);
        }
        __syncthreads();

        #pragma unroll
        for (int kk = 0; kk < 2; kk++) {
            uint32_t ah[4][4], al[4][4];
            const int arow = wm * 64 + (lane & 7) + ((lane >> 3) & 1) * 8;
            const int acol = kk * 16 + (lane >> 4) * 8;
            #pragma unroll
            for (int mf = 0; mf < 4; mf++) {
                ldsm4(ah[mf][0], ah[mf][1], ah[mf][2], ah[mf][3],
                      smem_u32(&Ah[(arow + mf * 16) * PLDA + acol]));
                ldsm4(al[mf][0], al[mf][1], al[mf][2], al[mf][3],
                      smem_u32(&Al[(arow + mf * 16) * PLDA + acol]));
            }
            uint32_t bh[4][2], bl[4][2];
            const int brow = kk * 16 + (lane & 7) + ((lane >> 3) & 1) * 8;
            #pragma unroll
            for (int nb = 0; nb < 2; nb++) {
                const int bcol = wn * 32 + nb * 16 + (lane >> 4) * 8;
                ldsm4t(bh[2*nb][0], bh[2*nb][1], bh[2*nb+1][0], bh[2*nb+1][1],
                       smem_u32(&Bh[brow * PLDB + bcol]));
                ldsm4t(bl[2*nb][0], bl[2*nb][1], bl[2*nb+1][0], bl[2*nb+1][1],
                       smem_u32(&Bl[brow * PLDB + bcol]));
            }
            #pragma unroll
            for (int mf = 0; mf < 4; mf++)
                #pragma unroll
                for (int nf = 0; nf < 4; nf++) {
                    mma_bf16(acc[mf][nf], ah[mf], bh[nf][0], bh[nf][1]);
                    mma_bf16(acc[mf][nf], ah[mf], bl[nf][0], bl[nf][1]);
                    mma_bf16(acc[mf][nf], al[mf], bh[nf][0], bh[nf][1]);
                }
        }
        __syncthreads();
    }

    const int g = lane >> 2, tq = lane & 3;
    #pragma unroll
    for (int mf = 0; mf < 4; mf++) {
        int r0 = m0 + wm * 64 + mf * 16 + g;
        int r1 = r0 + 8;
        #pragma unroll
        for (int nf = 0; nf < 4; nf++) {
            int n = n0 + wn * 32 + nf * 8 + tq * 2;
            float bia0 = bo[n], bia1 = bo[n + 1];
            *(float2*)&out[(size_t)r0 * H_ + n] =
                make_float2(acc[mf][nf][0] + bia0, acc[mf][nf][1] + bia1);
            *(float2*)&out[(size_t)r1 * H_ + n] =
                make_float2(acc[mf][nf][2] + bia0, acc[mf][nf][3] + bia1);
        }
    }
}

// ---------------------------------------------------------------------------
// Launch
// ---------------------------------------------------------------------------
extern "C" void kernel_launch(void* const* d_in, const int* in_sizes, int n_in,
                              void* d_out, int out_size)
{
    const float* X  = (const float*)d_in[0];
    const float* Wq = (const float*)d_in[1];
    const float* bq = (const float*)d_in[2];
    const float* Wk = (const float*)d_in[3];
    const float* bk = (const float*)d_in[4];
    const float* Wv = (const float*)d_in[5];
    const float* bv = (const float*)d_in[6];
    const float* Wo = (const float*)d_in[7];
    const float* bo = (const float*)d_in[8];
    float* out = (float*)d_out;

    static bool attr_set = false;
    if (!attr_set) {
        cudaFuncSetAttribute(attn_tc,
                             cudaFuncAttributeMaxDynamicSharedMemorySize,
                             ATT_SMEM_BYTES);
        attr_set = true;
    }

    dim3 gproj(H_ / 128, M_ / 128, 3);          // (8, 64, 3)
    qkv_gemm_tc<<<gproj, 256>>>(X, Wq, bq, Wk, bk, Wv, bv);

    dim3 gattn(S_ / 128, B_ * NH_);             // (16, 64)
    attn_tc<<<gattn, 256, ATT_SMEM_BYTES>>>();

    dim3 gout(H_ / 128, M_ / 128);              // (8, 64)
    oproj_tc<<<gout, 256>>>(Wo, bo, out);
}